// round 16
// baseline (speedup 1.0000x reference)
#include <cuda_runtime.h>
#include <cstdint>
#include <cmath>

// ---------------------------------------------------------------------------
// Head_55671366091048 (sm_103a), cta_group::2 tcgen05, warp-specialized.
//   Wc = rna(W)
//   q = rna(x) Wqc^T ; k = rna(y) Wkc^T ; vT = (rna(y) Wvc^T)^T  (fused z=3)
//   a = mask(q k^T) * d^-1/2    (strict lower; 256x256 pair-tiles, skip bn>bm)
//   part[c] = a[:, c*2048:(c+1)*2048] vT^T  (split-K)
//   out = sum_c part[c]
//
// Round-15 finding: every config is latency-bound (~3.7K cyc/tile, no unit
// >40%); depth is limited by smem. cg2 halves per-CTA bytes/tile (each CTA
// holds 128 A-rows + its 128 B-rows = 32KB/stage) -> S=6 stages, 6-deep
// lookahead. Cluster (2,1,1): pair computes one 256x256 tile; leader issues
// M=256 MMAs; followers relay full[s] via mapa cluster-arrive; commit
// multicasts done[s] to both CTAs.
// ---------------------------------------------------------------------------

#if defined(__CUDA_ARCH__) && defined(__CUDA_ARCH_FEAT_SM103_ALL)
#define USE_TCGEN05 1
#else
#define USE_TCGEN05 0
#endif

namespace {
constexpr int kNX = 8192;
constexpr int kNY = 8192;
constexpr int kC  = 2048;
constexpr int kD  = 512;

constexpr int BMC = 256;                 // pair rows (128 per CTA)
constexpr int BNC = 256;                 // pair cols (B split 128 per CTA)
constexpr int KT  = 32;                  // K per smem tile (128B rows)
constexpr int SS  = 6;                   // stages
constexpr int ABYTES = 128 * 128;        // 16 KB (this CTA's A half)
constexpr int BBYTES = 128 * 128;        // 16 KB (this CTA's B half)
constexpr int STB = ABYTES + BBYTES;     // 32 KB
constexpr int MBAR_OFF = 64;             // full[s] @ +16s, done[s] @ +16s+8
constexpr int DATA_OFF = 1024;
constexpr int SMEM_SZ = DATA_OFF + SS * STB;   // 197632 B

constexpr int NTHREADS = 288;            // 8 producer warps + 1 MMA warp
constexpr int KCHUNK = 2048;             // split-K chunk (stage 3)
constexpr size_t OUT_ELEMS = (size_t)kNX * kD;

constexpr uint64_t DESC_BASE =
    (uint64_t(2) << 61) | (uint64_t(1) << 46) | (uint64_t(64) << 32) |
    (uint64_t(1) << 16);

// idesc kind::tf32 cg2: dtype F32, a/b TF32, N=256, M=256 (M/16=16)
constexpr uint32_t IDESC =
    (1u << 4) | (2u << 7) | (2u << 10) | ((BNC / 8) << 17) | (16u << 24);
}  // namespace

__device__ float g_wqc[(size_t)kD * kC];
__device__ float g_wkc[(size_t)kD * kC];
__device__ float g_wvc[(size_t)kD * kC];
__device__ float g_q[(size_t)kNX * kD];
__device__ float g_k[(size_t)kNY * kD];
__device__ float g_vT[(size_t)kD * kNY];
__device__ float g_a[(size_t)kNX * kNY];
__device__ float g_part[4][OUT_ELEMS];

// ---------------------------------------------------------------------------
__device__ __forceinline__ uint32_t smem_u32(const void* p) {
  uint32_t a;
  asm("{ .reg .u64 t; cvta.to.shared.u64 t, %1; cvt.u32.u64 %0, t; }"
      : "=r"(a) : "l"(p));
  return a;
}
__device__ __forceinline__ uint32_t ctarank() {
  uint32_t r;
  asm("mov.u32 %0, %%cluster_ctarank;" : "=r"(r));
  return r;
}
__device__ __forceinline__ float tf32r(float f) {
  uint32_t u;
  asm("cvt.rna.tf32.f32 %0, %1;" : "=r"(u) : "f"(f));
  return __uint_as_float(u);
}
__device__ __forceinline__ float4 tf32r4(float4 v) {
  return make_float4(tf32r(v.x), tf32r(v.y), tf32r(v.z), tf32r(v.w));
}

__global__ void cvt_kernel(const float* s0, float* d0, const float* s1,
                           float* d1, const float* s2, float* d2, int n) {
  const int z = blockIdx.z;
  const float* s = (z == 0) ? s0 : (z == 1) ? s1 : s2;
  float* d = (z == 0) ? d0 : (z == 1) ? d1 : d2;
  int i = (blockIdx.x * blockDim.x + threadIdx.x) * 4;
  const int stride = gridDim.x * blockDim.x * 4;
  for (; i < n; i += stride) *(float4*)(d + i) = tf32r4(*(const float4*)(s + i));
}

__global__ void reduce_kernel(const float* __restrict__ part,
                              float* __restrict__ out) {
  const size_t i4 = ((size_t)blockIdx.x * blockDim.x + threadIdx.x) * 4;
  if (i4 >= OUT_ELEMS) return;
  const int row = (int)(i4 / kD);
  const int nch = row / KCHUNK + 1;
  float4 s = *(const float4*)(part + i4);
  for (int c = 1; c < nch; ++c) {
    const float4 p = *(const float4*)(part + (size_t)c * OUT_ELEMS + i4);
    s.x += p.x; s.y += p.y; s.z += p.z; s.w += p.w;
  }
  *(float4*)(out + i4) = s;
}

#if USE_TCGEN05
__device__ __forceinline__ void mbar_init(uint32_t addr, uint32_t cnt) {
  asm volatile("mbarrier.init.shared.b64 [%0], %1;" :: "r"(addr), "r"(cnt)
               : "memory");
}
__device__ __forceinline__ void mbar_inval(uint32_t addr) {
  asm volatile("mbarrier.inval.shared.b64 [%0];" :: "r"(addr) : "memory");
}
__device__ __forceinline__ void mbar_arrive(uint32_t addr) {
  asm volatile("mbarrier.arrive.shared.b64 _, [%0];" :: "r"(addr) : "memory");
}
// arrive on the same smem offset in cluster CTA 0 (the leader)
__device__ __forceinline__ void mbar_arrive_leader(uint32_t local_addr) {
  asm volatile(
      "{\n\t.reg .b32 ra;\n\t"
      "mapa.shared::cluster.u32 ra, %0, 0;\n\t"
      "mbarrier.arrive.shared::cluster.b64 _, [ra];\n\t}"
      :: "r"(local_addr) : "memory");
}
__device__ __forceinline__ void mbar_wait(uint32_t addr, uint32_t parity) {
  uint32_t done;
  asm volatile(
      "{\n\t.reg .pred p;\n\t"
      "mbarrier.try_wait.parity.acquire.cta.shared::cta.b64 p, [%1], %2;\n\t"
      "selp.b32 %0, 1, 0, p;\n\t}"
      : "=r"(done) : "r"(addr), "r"(parity) : "memory");
  if (!done) {
    asm volatile(
        "{\n\t.reg .pred P1;\n\t"
        "WL_%=:\n\t"
        "mbarrier.try_wait.parity.acquire.cta.shared::cta.b64 P1, [%0], %1, 0x989680;\n\t"
        "@P1 bra.uni WD_%=;\n\t"
        "bra.uni WL_%=;\n\t"
        "WD_%=:\n\t}"
        :: "r"(addr), "r"(parity) : "memory");
  }
}
__device__ __forceinline__ void tmem_alloc2(uint32_t smem_dst, uint32_t ncols) {
  asm volatile(
      "tcgen05.alloc.cta_group::2.sync.aligned.shared::cta.b32 [%0], %1;"
      :: "r"(smem_dst), "r"(ncols) : "memory");
}
__device__ __forceinline__ void tmem_relinq2() {
  asm volatile("tcgen05.relinquish_alloc_permit.cta_group::2.sync.aligned;");
}
__device__ __forceinline__ void tmem_dealloc2(uint32_t tmem, uint32_t ncols) {
  asm volatile("tcgen05.dealloc.cta_group::2.sync.aligned.b32 %0, %1;"
               :: "r"(tmem), "r"(ncols));
}
__device__ __forceinline__ void mma_tf32_cg2(uint32_t d, uint64_t ad,
                                             uint64_t bd, uint32_t idesc,
                                             bool accum) {
  uint32_t en = accum ? 1u : 0u;
  asm volatile(
      "{\n\t.reg .pred p;\n\t"
      "setp.ne.u32 p, %4, 0;\n\t"
      "tcgen05.mma.cta_group::2.kind::tf32 [%0], %1, %2, %3, "
      "{%5,%5,%5,%5,%5,%5,%5,%5}, p;\n\t}"
      :: "r"(d), "l"(ad), "l"(bd), "r"(idesc), "r"(en), "r"(0u) : "memory");
}
__device__ __forceinline__ void mma_commit_mc(uint32_t mbar) {
  asm volatile(
      "tcgen05.commit.cta_group::2.mbarrier::arrive::one.shared::cluster"
      ".multicast::cluster.b64 [%0], %1;"
      :: "r"(mbar), "h"((uint16_t)0x3) : "memory");
}
__device__ __forceinline__ void ldtm_x32(uint32_t* r, uint32_t addr) {
  asm volatile(
      "tcgen05.ld.sync.aligned.32x32b.x32.b32 "
      "{%0,%1,%2,%3,%4,%5,%6,%7,%8,%9,%10,%11,%12,%13,%14,%15,"
      "%16,%17,%18,%19,%20,%21,%22,%23,%24,%25,%26,%27,%28,%29,%30,%31}, [%32];"
      : "=r"(r[0]), "=r"(r[1]), "=r"(r[2]), "=r"(r[3]), "=r"(r[4]), "=r"(r[5]),
        "=r"(r[6]), "=r"(r[7]), "=r"(r[8]), "=r"(r[9]), "=r"(r[10]),
        "=r"(r[11]), "=r"(r[12]), "=r"(r[13]), "=r"(r[14]), "=r"(r[15]),
        "=r"(r[16]), "=r"(r[17]), "=r"(r[18]), "=r"(r[19]), "=r"(r[20]),
        "=r"(r[21]), "=r"(r[22]), "=r"(r[23]), "=r"(r[24]), "=r"(r[25]),
        "=r"(r[26]), "=r"(r[27]), "=r"(r[28]), "=r"(r[29]), "=r"(r[30]),
        "=r"(r[31])
      : "r"(addr));
}
__device__ __forceinline__ void cp16(uint32_t dst, const void* src) {
  asm volatile("cp.async.cg.shared.global [%0], [%1], 16;"
               :: "r"(dst), "l"(src) : "memory");
}
__device__ __forceinline__ void cp_arrive_noinc(uint32_t mbar) {
  asm volatile("cp.async.mbarrier.arrive.noinc.shared.b64 [%0];"
               :: "r"(mbar) : "memory");
}
#endif  // USE_TCGEN05

#define SWZ(o) ((o) ^ (((o) >> 3) & 0x70))
#define CLUSTER_SYNC_()                                            \
  do {                                                             \
    asm volatile("barrier.cluster.arrive.aligned;" ::: "memory");  \
    asm volatile("barrier.cluster.wait.aligned;" ::: "memory");    \
  } while (0)

// ---------------------------------------------------------------------------
// cg2 pair GEMM: pair computes C[256,256] = A[256,K] B[256,K]^T tile.
// CTA rank r holds A rows [row0+128r, +128) and B rows [col0+128r, +128).
// MODE 2: skip bn>bm; mask+scale epilogue. MODE 4: fused projections (A via
// LDG->rna->STS), z=0 q / z=1 k / z=2 vT(transposed). MODE 5: split-K.
// ---------------------------------------------------------------------------
template <int MODE>
__global__ void __launch_bounds__(NTHREADS, 1) __cluster_dims__(2, 1, 1)
tc2(const float* A, const float* B, float* C,
    const float* Ay, const float* Bk, float* Ck,
    const float* Bv, float* Cv,
    int M, int N, int K, float scale) {
  int tmode = MODE;
  if (MODE == 4) {
    const int z = blockIdx.z;
    if (z == 0)      { tmode = 0; }
    else if (z == 1) { A = Ay; B = Bk; C = Ck; tmode = 0; }
    else             { A = Ay; B = Bv; C = Cv; tmode = 1; }
  }
  const int bn = blockIdx.x >> 1;
  const int bm = blockIdx.y;
  if (MODE == 2 && bn > bm) return;

  int kstart = 0, kend = K;
  if (MODE == 5) {
    const int Keff = min(K, (bm + 1) * BMC);
    kstart = blockIdx.z * KCHUNK;
    kend = min(Keff, kstart + KCHUNK);
    if (kstart >= Keff) return;
    C += (size_t)blockIdx.z * OUT_ELEMS;
  }
  const int row0 = bm * BMC, col0 = bn * BNC;
  const int nT = (kend - kstart) / KT;
  extern __shared__ char smem[];
  const int tid = threadIdx.x;
  const int wid = tid >> 5;

#if USE_TCGEN05
  const uint32_t sb = smem_u32(smem);
  const uint32_t rank = ctarank();
  // local producer arrivals: 256 cp (+256 STS arrives in MODE 4);
  // leader additionally receives 1 relay arrive from the follower.
  const uint32_t full_cnt =
      ((MODE == 4) ? 512u : 256u) + ((rank == 0) ? 1u : 0u);

  if (wid == 8) { tmem_alloc2(sb, 256); tmem_relinq2(); }
  if (tid == 0) {
#pragma unroll
    for (int s = 0; s < SS; ++s) {
      mbar_init(sb + MBAR_OFF + 16 * s, full_cnt);     // full[s]
      mbar_init(sb + MBAR_OFF + 16 * s + 8, 1);        // done[s] (mc commit)
    }
  }
  __syncthreads();
  CLUSTER_SYNC_();   // peer mbars live before any cross-CTA arrive/MMA
  uint32_t tmem;
  asm volatile("ld.shared.b32 %0, [%1];" : "=r"(tmem) : "r"(sb));

  if (tid < 256) {
    // ---- producers: this CTA's 128 A-rows and 128 B-rows, coalesced ----
    const int r0  = tid >> 3;          // 0..31
    const int c16 = tid & 7;
    const float* Ag =
        A + (size_t)(row0 + rank * 128 + r0) * K + kstart + c16 * 4;
    const float* Bg =
        B + (size_t)(col0 + rank * 128 + r0) * K + kstart + c16 * 4;
    const size_t rstep = (size_t)32 * K;
    const int swb = SWZ(r0 * 128 + c16 * 16);

    for (int t = 0; t < nT; ++t) {
      const int s = t % SS;
      if (t >= SS) mbar_wait(sb + MBAR_OFF + 16 * s + 8, ((t / SS) - 1) & 1);
      const uint32_t base = sb + DATA_OFF + s * STB;

      if (MODE == 4) {
        const float* ap = Ag + (size_t)t * KT;
        float4 v[4];
#pragma unroll
        for (int i = 0; i < 4; ++i) v[i] = *(const float4*)(ap + i * rstep);
        char* d = smem + DATA_OFF + s * STB + swb;
#pragma unroll
        for (int i = 0; i < 4; ++i) *(float4*)(d + i * 4096) = tf32r4(v[i]);
      } else {
        const float* ap = Ag + (size_t)t * KT;
#pragma unroll
        for (int i = 0; i < 4; ++i) cp16(base + swb + i * 4096, ap + i * rstep);
      }
      {
        const float* bp = Bg + (size_t)t * KT;
#pragma unroll
        for (int i = 0; i < 4; ++i)
          cp16(base + ABYTES + swb + i * 4096, bp + i * rstep);
      }
      if (MODE == 4) {
        asm volatile("fence.proxy.async;" ::: "memory");
        mbar_arrive(sb + MBAR_OFF + 16 * s);            // release STS
      }
      cp_arrive_noinc(sb + MBAR_OFF + 16 * s);          // cp completion
    }

    // ---- epilogue: this CTA's 128 rows x 256 cols from its TMEM ----
    mbar_wait(sb + MBAR_OFF + 16 * ((nT - 1) % SS) + 8, ((nT - 1) / SS) & 1);
    asm volatile("tcgen05.fence::after_thread_sync;" ::: "memory");

    const int wg = tid >> 7, sp = (tid >> 5) & 3, lane = tid & 31;
    const int row = row0 + rank * 128 + sp * 32 + lane;
    uint32_t r[32];
#pragma unroll
    for (int ch = 0; ch < 4; ++ch) {
      const int colb = wg * 128 + ch * 32;
      ldtm_x32(r, tmem + colb);
      asm volatile("tcgen05.wait::ld.sync.aligned;" ::: "memory");
      if (tmode == 1) {
#pragma unroll
        for (int j = 0; j < 32; ++j)
          C[(size_t)(col0 + colb + j) * M + row] = tf32r(__uint_as_float(r[j]));
      } else if (tmode == 2) {
        float* cp = C + (size_t)row * N + col0 + colb;
#pragma unroll
        for (int j = 0; j < 32; ++j) {
          const int c = col0 + colb + j;
          cp[j] = (c >= row) ? 0.0f : tf32r(__uint_as_float(r[j]) * scale);
        }
      } else if (tmode == 0) {
        float* cp = C + (size_t)row * N + col0 + colb;
#pragma unroll
        for (int j = 0; j < 32; ++j) cp[j] = tf32r(__uint_as_float(r[j]));
      } else {
        float* cp = C + (size_t)row * N + col0 + colb;
#pragma unroll
        for (int j = 0; j < 32; ++j) cp[j] = __uint_as_float(r[j]);
      }
    }
  } else {
    // ---- warp 8: leader issues MMAs; follower relays full[s] ----
    const int lane = tid & 31;
    if (rank == 0) {
      for (int t = 0; t < nT; ++t) {
        const int s = t % SS;
        mbar_wait(sb + MBAR_OFF + 16 * s, (t / SS) & 1);
        if (lane == 0) {
          asm volatile("fence.proxy.async;" ::: "memory");
          const uint32_t base = sb + DATA_OFF + s * STB;
          const uint64_t ad = DESC_BASE | ((base >> 4) & 0x3FFF);
          const uint64_t bd = DESC_BASE | (((base + ABYTES) >> 4) & 0x3FFF);
#pragma unroll
          for (int ks = 0; ks < 4; ++ks)
            mma_tf32_cg2(tmem, ad + 2 * ks, bd + 2 * ks, IDESC,
                         (t > 0) || (ks > 0));
          mma_commit_mc(sb + MBAR_OFF + 16 * s + 8);
        }
        __syncwarp();
      }
    } else {
      for (int t = 0; t < nT; ++t) {
        const int s = t % SS;
        mbar_wait(sb + MBAR_OFF + 16 * s, (t / SS) & 1);
        if (lane == 0) {
          asm volatile("fence.proxy.async;" ::: "memory");
          mbar_arrive_leader(sb + MBAR_OFF + 16 * s);   // relay to leader
        }
        __syncwarp();
      }
      // follower's stage-reuse gating is via its local done[s] (multicast).
    }
  }

  __syncthreads();
  CLUSTER_SYNC_();   // all MMA reads of peer smem done before teardown
  if (tid == 0) {
#pragma unroll
    for (int s = 0; s < SS; ++s) {
      mbar_inval(sb + MBAR_OFF + 16 * s);
      mbar_inval(sb + MBAR_OFF + 16 * s + 8);
    }
  }
  if (wid == 8) tmem_dealloc2(tmem, 256);
  CLUSTER_SYNC_();

#elif defined(__CUDA_ARCH__)
  (void)smem; (void)nT; (void)wid;
  // fallback: each CTA computes its own 128 rows x 256 cols
  const int rank = blockIdx.x & 1;
  for (int e = tid; e < 128 * BNC; e += blockDim.x) {
    const int rr = row0 + rank * 128 + e / BNC;
    const int cc = col0 + e % BNC;
    float s = 0.f;
    for (int kk = kstart; kk < kend; ++kk)
      s += A[(size_t)rr * K + kk] * B[(size_t)cc * K + kk];
    if (tmode == 2) s = (cc >= rr) ? 0.f : s * scale;
    if (tmode == 1) C[(size_t)cc * M + rr] = s;
    else            C[(size_t)rr * N + cc] = s;
  }
#endif
}

// ---------------------------------------------------------------------------

extern "C" void kernel_launch(void* const* d_in, const int* in_sizes, int n_in,
                              void* d_out, int out_size) {
  (void)in_sizes; (void)n_in; (void)out_size;
  const float* x  = (const float*)d_in[0];
  const float* y  = (const float*)d_in[1];
  const float* Wq = (const float*)d_in[2];
  const float* Wk = (const float*)d_in[3];
  const float* Wv = (const float*)d_in[4];
  float* out = (float*)d_out;

  float *wqc, *wkc, *wvc, *q, *k, *vT, *a, *part;
  cudaGetSymbolAddress((void**)&wqc, g_wqc);
  cudaGetSymbolAddress((void**)&wkc, g_wkc);
  cudaGetSymbolAddress((void**)&wvc, g_wvc);
  cudaGetSymbolAddress((void**)&q, g_q);
  cudaGetSymbolAddress((void**)&k, g_k);
  cudaGetSymbolAddress((void**)&vT, g_vT);
  cudaGetSymbolAddress((void**)&a, g_a);
  cudaGetSymbolAddress((void**)&part, g_part);

  cudaFuncSetAttribute(tc2<2>, cudaFuncAttributeMaxDynamicSharedMemorySize,
                       SMEM_SZ);
  cudaFuncSetAttribute(tc2<4>, cudaFuncAttributeMaxDynamicSharedMemorySize,
                       SMEM_SZ);
  cudaFuncSetAttribute(tc2<5>, cudaFuncAttributeMaxDynamicSharedMemorySize,
                       SMEM_SZ);

  dim3 blk(NTHREADS, 1, 1);
  const float scale = 1.0f / sqrtf((float)kD);

  // Stage 0: RNE-convert weights (12 MB)
  cvt_kernel<<<dim3(64, 1, 3), dim3(256, 1, 1)>>>(Wq, wqc, Wk, wkc, Wv, wvc,
                                                  kD * kC);

  // Stage 1: fused projections q, k, vT (pairs along x; x = 2 * kD/256)
  tc2<4><<<dim3(2 * (kD / BNC), kNX / BMC, 3), blk, SMEM_SZ>>>(
      x, wqc, q, y, wkc, k, wvc, vT, kNX, kD, kC, 1.0f);

  // Stage 2: a = mask(q k^T)*scale (skip bn>bm at 256 granularity)
  tc2<2><<<dim3(2 * (kNY / BNC), kNX / BMC), blk, SMEM_SZ>>>(
      q, k, a, nullptr, nullptr, nullptr, nullptr, nullptr,
      kNX, kNY, kD, scale);

  // Stage 3: split-K partials, then fixed-order reduce
  tc2<5><<<dim3(2 * (kD / BNC), kNX / BMC, kNY / KCHUNK), blk, SMEM_SZ>>>(
      a, vT, part, nullptr, nullptr, nullptr, nullptr, nullptr,
      kNX, kD, kNY, 1.0f);
  reduce_kernel<<<(int)(OUT_ELEMS / 4 + 255) / 256, 256>>>(part, out);
}

// round 17
// speedup vs baseline: 1.5618x; 1.5618x over previous
#include <cuda_runtime.h>
#include <cstdint>
#include <cmath>

// ---------------------------------------------------------------------------
// Head_55671366091048 (sm_103a):
//   xc/yc/Wc = rna(x/y/W)   (ONE fused full-chip cvt launch, z=5 planes)
//   q = xc Wqc^T ; k = yc Wkc^T ; vT = (yc Wvc^T)^T    (one fused launch)
//   a = mask(q k^T) * d^-1/2    (strict lower; 128x128 blocks, skip bn>bm)
//   out = a vT^T                (per-128-row K limit, reversed bm)
//
// This is the round-5 kernel (best measured: 541.8us) byte-for-byte, with
// the only change being the cvt pre-pass consolidated from 5 low-occupancy
// launches (~95us) into one z=5 full-chip launch (~50us). Rounds 6-16
// established that every alternative architecture (bigger tiles, 2 CTA/SM,
// warp spec, split-K, cg2) pays coordination taxes exceeding its wins;
// protect the best kernel, harvest the measured inefficiency.
// tcgen05 kind::tf32 SS MMA, 128x128 tiles, 6-stage cp.async pipeline,
// PF=4 prefetch distance. compute_103 PTX pass gets an mma.sync fallback.
// ---------------------------------------------------------------------------

#if defined(__CUDA_ARCH__) && defined(__CUDA_ARCH_FEAT_SM103_ALL)
#define USE_TCGEN05 1
#else
#define USE_TCGEN05 0
#endif

namespace {
constexpr int kNX = 8192;
constexpr int kNY = 8192;
constexpr int kC  = 2048;
constexpr int kD  = 512;

constexpr int BM = 128;
constexpr int BN = 128;

constexpr int KT = 32;                      // K elems per smem tile (128B rows)
constexpr int S  = 6;                       // pipeline stages
constexpr int PF = 4;                       // prefetch distance (tiles ahead)
constexpr int TILE_BYTES  = 128 * 128;      // one operand tile (16 KB)
constexpr int STAGE_BYTES = 2 * TILE_BYTES; // A + B (32 KB)
constexpr int MBAR_OFF  = 64;
constexpr int DATA_OFF  = 1024;
constexpr int SMEM_TOTAL = DATA_OFF + S * STAGE_BYTES;  // ~193 KB

// fallback path
constexpr int FBK  = 16;
constexpr int ASTR = FBK + 4;

// SW128 K-major smem descriptor base (layout=2, version=1, SBO=64, LBO=1)
constexpr uint64_t DESC_BASE =
    (uint64_t(2) << 61) | (uint64_t(1) << 46) | (uint64_t(64) << 32) |
    (uint64_t(1) << 16);

// idesc kind::tf32: dtype F32=1<<4, atype TF32=2<<7, btype TF32=2<<10,
// N/8 at [17:22], M/16 at [24:28]
constexpr uint32_t IDESC =
    (1u << 4) | (2u << 7) | (2u << 10) | ((BN / 8) << 17) | ((BM / 16) << 24);
}  // namespace

// scratch (no allocations allowed anywhere)
__device__ float g_xc[(size_t)kNX * kC];
__device__ float g_yc[(size_t)kNY * kC];
__device__ float g_wqc[(size_t)kD * kC];
__device__ float g_wkc[(size_t)kD * kC];
__device__ float g_wvc[(size_t)kD * kC];
__device__ float g_q[(size_t)kNX * kD];
__device__ float g_k[(size_t)kNY * kD];
__device__ float g_vT[(size_t)kD * kNY];
__device__ float g_a[(size_t)kNX * kNY];

// ---------------------------------------------------------------------------
// helpers
// ---------------------------------------------------------------------------
__device__ __forceinline__ uint32_t smem_u32(const void* p) {
  uint32_t a;
  asm("{ .reg .u64 t; cvta.to.shared.u64 t, %1; cvt.u32.u64 %0, t; }"
      : "=r"(a) : "l"(p));
  return a;
}
__device__ __forceinline__ float tf32r(float f) {
  uint32_t u;
  asm("cvt.rna.tf32.f32 %0, %1;" : "=r"(u) : "f"(f));
  return __uint_as_float(u);
}
__device__ __forceinline__ float4 tf32r4(float4 v) {
  return make_float4(tf32r(v.x), tf32r(v.y), tf32r(v.z), tf32r(v.w));
}

// ONE launch converts all five tensors: z selects the plane.
__global__ void cvt5_kernel(const float* x, float* xc, const float* y,
                            float* yc, const float* wq, float* wqc,
                            const float* wk, float* wkc, const float* wv,
                            float* wvc, int nxy, int nw) {
  const int z = blockIdx.z;
  const float* s;
  float* d;
  int n;
  if (z == 0)      { s = x;  d = xc;  n = nxy; }
  else if (z == 1) { s = y;  d = yc;  n = nxy; }
  else if (z == 2) { s = wq; d = wqc; n = nw; }
  else if (z == 3) { s = wk; d = wkc; n = nw; }
  else             { s = wv; d = wvc; n = nw; }
  int i = (blockIdx.x * blockDim.x + threadIdx.x) * 4;
  const int stride = gridDim.x * blockDim.x * 4;
  for (; i < n; i += stride) *(float4*)(d + i) = tf32r4(*(const float4*)(s + i));
}

#if USE_TCGEN05
__device__ __forceinline__ void mbar_init(uint32_t addr, uint32_t cnt) {
  asm volatile("mbarrier.init.shared.b64 [%0], %1;" :: "r"(addr), "r"(cnt)
               : "memory");
}
__device__ __forceinline__ void mbar_inval(uint32_t addr) {
  asm volatile("mbarrier.inval.shared.b64 [%0];" :: "r"(addr) : "memory");
}
__device__ __forceinline__ void mbar_wait(uint32_t addr, uint32_t parity) {
  uint32_t done;
  asm volatile(
      "{\n\t.reg .pred p;\n\t"
      "mbarrier.try_wait.parity.acquire.cta.shared::cta.b64 p, [%1], %2;\n\t"
      "selp.b32 %0, 1, 0, p;\n\t}"
      : "=r"(done) : "r"(addr), "r"(parity) : "memory");
  if (!done) {
    asm volatile(
        "{\n\t.reg .pred P1;\n\t"
        "WL_%=:\n\t"
        "mbarrier.try_wait.parity.acquire.cta.shared::cta.b64 P1, [%0], %1, 0x989680;\n\t"
        "@P1 bra.uni WD_%=;\n\t"
        "bra.uni WL_%=;\n\t"
        "WD_%=:\n\t}"
        :: "r"(addr), "r"(parity) : "memory");
  }
}
__device__ __forceinline__ void tmem_alloc(uint32_t smem_dst, uint32_t ncols) {
  asm volatile(
      "tcgen05.alloc.cta_group::1.sync.aligned.shared::cta.b32 [%0], %1;"
      :: "r"(smem_dst), "r"(ncols) : "memory");
}
__device__ __forceinline__ void tmem_relinq() {
  asm volatile("tcgen05.relinquish_alloc_permit.cta_group::1.sync.aligned;");
}
__device__ __forceinline__ void tmem_dealloc(uint32_t tmem, uint32_t ncols) {
  asm volatile("tcgen05.dealloc.cta_group::1.sync.aligned.b32 %0, %1;"
               :: "r"(tmem), "r"(ncols));
}
__device__ __forceinline__ void mma_tf32(uint32_t d, uint64_t ad, uint64_t bd,
                                         uint32_t idesc, bool accum) {
  uint32_t en = accum ? 1u : 0u;
  asm volatile(
      "{\n\t.reg .pred p;\n\t"
      "setp.ne.u32 p, %4, 0;\n\t"
      "tcgen05.mma.cta_group::1.kind::tf32 [%0], %1, %2, %3, {%5,%5,%5,%5}, p;\n\t}"
      :: "r"(d), "l"(ad), "l"(bd), "r"(idesc), "r"(en), "r"(0u) : "memory");
}
__device__ __forceinline__ void mma_commit(uint32_t mbar) {
  asm volatile(
      "tcgen05.commit.cta_group::1.mbarrier::arrive::one.shared::cluster.b64 [%0];"
      :: "r"(mbar) : "memory");
}
__device__ __forceinline__ void ldtm_x32(uint32_t* r, uint32_t addr) {
  asm volatile(
      "tcgen05.ld.sync.aligned.32x32b.x32.b32 "
      "{%0,%1,%2,%3,%4,%5,%6,%7,%8,%9,%10,%11,%12,%13,%14,%15,"
      "%16,%17,%18,%19,%20,%21,%22,%23,%24,%25,%26,%27,%28,%29,%30,%31}, [%32];"
      : "=r"(r[0]), "=r"(r[1]), "=r"(r[2]), "=r"(r[3]), "=r"(r[4]), "=r"(r[5]),
        "=r"(r[6]), "=r"(r[7]), "=r"(r[8]), "=r"(r[9]), "=r"(r[10]),
        "=r"(r[11]), "=r"(r[12]), "=r"(r[13]), "=r"(r[14]), "=r"(r[15]),
        "=r"(r[16]), "=r"(r[17]), "=r"(r[18]), "=r"(r[19]), "=r"(r[20]),
        "=r"(r[21]), "=r"(r[22]), "=r"(r[23]), "=r"(r[24]), "=r"(r[25]),
        "=r"(r[26]), "=r"(r[27]), "=r"(r[28]), "=r"(r[29]), "=r"(r[30]),
        "=r"(r[31])
      : "r"(addr));
}
__device__ __forceinline__ void cp16(uint32_t dst, const void* src) {
  asm volatile("cp.async.cg.shared.global [%0], [%1], 16;"
               :: "r"(dst), "l"(src) : "memory");
}
#endif  // USE_TCGEN05

#if !USE_TCGEN05 && defined(__CUDA_ARCH__)
__device__ __forceinline__ void mma8(float* c, const uint32_t* a,
                                     const uint32_t* b) {
  asm volatile(
      "mma.sync.aligned.m16n8k8.row.col.f32.tf32.tf32.f32 "
      "{%0,%1,%2,%3}, {%4,%5,%6,%7}, {%8,%9}, {%0,%1,%2,%3};\n"
      : "+f"(c[0]), "+f"(c[1]), "+f"(c[2]), "+f"(c[3])
      : "r"(a[0]), "r"(a[1]), "r"(a[2]), "r"(a[3]), "r"(b[0]), "r"(b[1]));
}
#endif

#define SWZ(o) ((o) ^ (((o) >> 3) & 0x70))

// ---------------------------------------------------------------------------
// NT GEMM, runtime mode:
//  0: store tf32-rounded         1: transposed store C[N,M], tf32-rounded
//  2: strict causal mask*scale (tf32-rounded), skip bn>bm
//  3: K limited to (bm+1)*128, raw f32 store, bm order reversed
// fused!=0: blockIdx.z picks (A0,B0,C0,0)/(A1,B1,C1,0)/(A2,B2,C2,1)
// ---------------------------------------------------------------------------
__global__ void __launch_bounds__(256, 1)
tc_gemm_k(const float* __restrict__ A0, const float* __restrict__ B0, float* __restrict__ C0,
          const float* A1, const float* B1, float* C1,
          const float* A2, const float* B2, float* C2,
          int M, int N, int K, float scale, int fused, int mode0) {
  const float* A = A0; const float* B = B0; float* C = C0;
  int mode = mode0;
  if (fused) {
    const int z = blockIdx.z;
    if (z == 1)      { A = A1; B = B1; C = C1; }
    else if (z == 2) { A = A2; B = B2; C = C2; mode = 1; }
  }
  int bm = blockIdx.y;
  const int bn = blockIdx.x;
  if (mode == 3) bm = gridDim.y - 1 - bm;   // heavy rows first
  if (mode == 2 && bn > bm) return;

  const int Keff = (mode == 3) ? min(K, (bm + 1) * BM) : K;
  const int row0 = bm * BM, col0 = bn * BN;
  extern __shared__ char smem[];
  const int tid = threadIdx.x;

#if USE_TCGEN05
  // =========================================================================
  // tcgen05: cp.async producer (inputs pre-rounded to tf32), 6-stage pipe
  // =========================================================================
  const uint32_t sb = smem_u32(smem);
  const int nT = Keff / KT;   // >= 4 always

  if (tid < 32) {
    tmem_alloc(sb, 128);
    tmem_relinq();
  }
  if (tid == 0) {
#pragma unroll
    for (int s = 0; s < S; ++s) mbar_init(sb + MBAR_OFF + 8 * s, 1);
  }
  __syncthreads();
  uint32_t tmem;
  asm volatile("ld.shared.b32 %0, [%1];" : "=r"(tmem) : "r"(sb));

  // producer mapping: 4 x 16B per operand tile per thread
  const int r0  = tid >> 3;   // rows r0, +32, +64, +96
  const int c16 = tid & 7;
  const float* Ag = A + (size_t)(row0 + r0) * K + c16 * 4;
  const float* Bg = B + (size_t)(col0 + r0) * K + c16 * 4;
  const size_t rstep = (size_t)32 * K;
  const int swb = SWZ(r0 * 128 + c16 * 16);

  // prologue: tiles 0..PF-1 into stages 0..PF-1, one commit group each
#pragma unroll
  for (int u = 0; u < PF; ++u) {
    const uint32_t da = sb + DATA_OFF + u * STAGE_BYTES + swb;
    const float* ag = Ag + (size_t)u * KT;
    const float* bg = Bg + (size_t)u * KT;
#pragma unroll
    for (int i = 0; i < 4; ++i) {
      cp16(da + i * 4096, ag + i * rstep);
      cp16(da + TILE_BYTES + i * 4096, bg + i * rstep);
    }
    asm volatile("cp.async.commit_group;" ::: "memory");
  }

  for (int t = 0; t < nT; ++t) {
    const int u = t + PF;
    if (u < nT) {
      const int su = u % S;
      if (u >= S) {  // stage reuse: wait MMA of tile u-S (= t-2) done
        mbar_wait(sb + MBAR_OFF + 8 * su, ((u - S) / S) & 1);
      }
      const uint32_t da = sb + DATA_OFF + su * STAGE_BYTES + swb;
      const float* ag = Ag + (size_t)u * KT;
      const float* bg = Bg + (size_t)u * KT;
#pragma unroll
      for (int i = 0; i < 4; ++i) {
        cp16(da + i * 4096, ag + i * rstep);
        cp16(da + TILE_BYTES + i * 4096, bg + i * rstep);
      }
    }
    asm volatile("cp.async.commit_group;" ::: "memory");
    asm volatile("cp.async.wait_group 4;" ::: "memory");  // tile t complete
    asm volatile("fence.proxy.async.shared::cta;" ::: "memory");
    __syncthreads();

    if (tid == 0) {
      const int s = t % S;
      const uint32_t abase = sb + DATA_OFF + s * STAGE_BYTES;
      const uint64_t ad = DESC_BASE | ((abase >> 4) & 0x3FFF);
      const uint64_t bd = DESC_BASE | (((abase + TILE_BYTES) >> 4) & 0x3FFF);
#pragma unroll
      for (int ks = 0; ks < 4; ++ks)
        mma_tf32(tmem, ad + 2 * ks, bd + 2 * ks, IDESC, (t > 0) || (ks > 0));
      mma_commit(sb + MBAR_OFF + 8 * s);
    }
  }

  // epilogue
  mbar_wait(sb + MBAR_OFF + 8 * ((nT - 1) % S), ((nT - 1) / S) & 1);
  asm volatile("tcgen05.fence::after_thread_sync;" ::: "memory");

  const int wg   = tid >> 7;
  const int sp   = (tid >> 5) & 3;
  const int lane = tid & 31;
  const int row  = row0 + sp * 32 + lane;

  uint32_t r[32];
#pragma unroll
  for (int h = 0; h < 2; ++h) {
    const int colb = wg * 64 + h * 32;
    ldtm_x32(r, tmem + colb);
    asm volatile("tcgen05.wait::ld.sync.aligned;" ::: "memory");
    asm volatile("tcgen05.fence::before_thread_sync;" ::: "memory");
    if (mode == 1) {
#pragma unroll
      for (int j = 0; j < 32; ++j)
        C[(size_t)(col0 + colb + j) * M + row] = tf32r(__uint_as_float(r[j]));
    } else if (mode == 2) {
      float* cp = C + (size_t)row * N + col0 + colb;
#pragma unroll
      for (int j = 0; j < 32; ++j) {
        const int c = col0 + colb + j;
        cp[j] = (c >= row) ? 0.0f : tf32r(__uint_as_float(r[j]) * scale);
      }
    } else if (mode == 0) {
      float* cp = C + (size_t)row * N + col0 + colb;
#pragma unroll
      for (int j = 0; j < 32; ++j) cp[j] = tf32r(__uint_as_float(r[j]));
    } else {
      float* cp = C + (size_t)row * N + col0 + colb;
#pragma unroll
      for (int j = 0; j < 32; ++j) cp[j] = __uint_as_float(r[j]);
    }
  }

  __syncthreads();
  if (tid == 0) {
#pragma unroll
    for (int s = 0; s < S; ++s) mbar_inval(sb + MBAR_OFF + 8 * s);
  }
  if (tid < 32) tmem_dealloc(tmem, 128);

#elif defined(__CUDA_ARCH__)
  // =========================================================================
  // Fallback (compute_103 pass): mma.sync m16n8k8 tf32, runtime mode
  // =========================================================================
  float* As = (float*)smem;
  float* Bs = As + 2 * BM * ASTR;

  const int lr = tid >> 2, lc = (tid & 3) * 4;
  const float* Ag0 = A + (size_t)(row0 + lr) * K + lc;
  const float* Ag1 = A + (size_t)(row0 + lr + 64) * K + lc;
  const float* Bg0 = B + (size_t)(col0 + lr) * K + lc;
  const float* Bg1 = B + (size_t)(col0 + lr + 64) * K + lc;

  const int lane = tid & 31, wid = tid >> 5;
  const int wm = (wid & 3) * 32, wn = (wid >> 2) * 64;
  const int grp = lane >> 2, tig = lane & 3;

  float acc[2][8][4];
#pragma unroll
  for (int i = 0; i < 2; i++)
#pragma unroll
    for (int j = 0; j < 8; j++)
#pragma unroll
      for (int l = 0; l < 4; l++) acc[i][j][l] = 0.f;

  float4 pa0 = *(const float4*)Ag0;
  float4 pa1 = *(const float4*)Ag1;
  float4 pb0 = *(const float4*)Bg0;
  float4 pb1 = *(const float4*)Bg1;
  *(float4*)&As[lr * ASTR + lc]        = tf32r4(pa0);
  *(float4*)&As[(lr + 64) * ASTR + lc] = tf32r4(pa1);
  *(float4*)&Bs[lr * ASTR + lc]        = tf32r4(pb0);
  *(float4*)&Bs[(lr + 64) * ASTR + lc] = tf32r4(pb1);
  __syncthreads();

  const int nT = Keff / FBK;
  int cur = 0;
  for (int t = 0; t < nT; ++t) {
    if (t + 1 < nT) {
      const int ko = (t + 1) * FBK;
      pa0 = *(const float4*)(Ag0 + ko);
      pa1 = *(const float4*)(Ag1 + ko);
      pb0 = *(const float4*)(Bg0 + ko);
      pb1 = *(const float4*)(Bg1 + ko);
    }
    float* Ac = As + cur * BM * ASTR;
    float* Bc = Bs + cur * BN * ASTR;
#pragma unroll
    for (int kk = 0; kk < FBK; kk += 8) {
      uint32_t af[2][4];
#pragma unroll
      for (int mf = 0; mf < 2; ++mf) {
        const float* ap = &Ac[(wm + mf * 16 + grp) * ASTR + kk + tig];
        af[mf][0] = __float_as_uint(ap[0]);
        af[mf][1] = __float_as_uint(ap[8 * ASTR]);
        af[mf][2] = __float_as_uint(ap[4]);
        af[mf][3] = __float_as_uint(ap[8 * ASTR + 4]);
      }
#pragma unroll
      for (int nf = 0; nf < 8; ++nf) {
        const float* bp = &Bc[(wn + nf * 8 + grp) * ASTR + kk + tig];
        uint32_t bf[2];
        bf[0] = __float_as_uint(bp[0]);
        bf[1] = __float_as_uint(bp[4]);
        mma8(acc[0][nf], af[0], bf);
        mma8(acc[1][nf], af[1], bf);
      }
    }
    if (t + 1 < nT) {
      const int nxt = cur ^ 1;
      float* An = As + nxt * BM * ASTR;
      float* Bn = Bs + nxt * BN * ASTR;
      *(float4*)&An[lr * ASTR + lc]        = tf32r4(pa0);
      *(float4*)&An[(lr + 64) * ASTR + lc] = tf32r4(pa1);
      *(float4*)&Bn[lr * ASTR + lc]        = tf32r4(pb0);
      *(float4*)&Bn[(lr + 64) * ASTR + lc] = tf32r4(pb1);
      __syncthreads();
      cur = nxt;
    }
  }

#pragma unroll
  for (int mf = 0; mf < 2; ++mf)
#pragma unroll
    for (int nf = 0; nf < 8; ++nf) {
      const int r = row0 + wm + mf * 16 + grp;
      const int c = col0 + wn + nf * 8 + tig * 2;
      float v[4] = {acc[mf][nf][0], acc[mf][nf][1], acc[mf][nf][2],
                    acc[mf][nf][3]};
      if (mode == 2) {
        v[0] = (c     >= r)     ? 0.f : tf32r(v[0] * scale);
        v[1] = (c + 1 >= r)     ? 0.f : tf32r(v[1] * scale);
        v[2] = (c     >= r + 8) ? 0.f : tf32r(v[2] * scale);
        v[3] = (c + 1 >= r + 8) ? 0.f : tf32r(v[3] * scale);
      } else if (mode == 0 || mode == 1) {
        v[0] = tf32r(v[0]); v[1] = tf32r(v[1]);
        v[2] = tf32r(v[2]); v[3] = tf32r(v[3]);
      }
      if (mode == 1) {
        C[(size_t)c * M + r]           = v[0];
        C[(size_t)(c + 1) * M + r]     = v[1];
        C[(size_t)c * M + r + 8]       = v[2];
        C[(size_t)(c + 1) * M + r + 8] = v[3];
      } else {
        float* cp = C + (size_t)r * N + c;
        cp[0] = v[0];
        cp[1] = v[1];
        cp[(size_t)8 * N]     = v[2];
        cp[(size_t)8 * N + 1] = v[3];
      }
    }
#endif
}

// ---------------------------------------------------------------------------

extern "C" void kernel_launch(void* const* d_in, const int* in_sizes, int n_in,
                              void* d_out, int out_size) {
  (void)in_sizes; (void)n_in; (void)out_size;
  const float* x  = (const float*)d_in[0];
  const float* y  = (const float*)d_in[1];
  const float* Wq = (const float*)d_in[2];
  const float* Wk = (const float*)d_in[3];
  const float* Wv = (const float*)d_in[4];
  float* out = (float*)d_out;

  float *xc, *yc, *wqc, *wkc, *wvc, *q, *k, *vT, *a;
  cudaGetSymbolAddress((void**)&xc, g_xc);
  cudaGetSymbolAddress((void**)&yc, g_yc);
  cudaGetSymbolAddress((void**)&wqc, g_wqc);
  cudaGetSymbolAddress((void**)&wkc, g_wkc);
  cudaGetSymbolAddress((void**)&wvc, g_wvc);
  cudaGetSymbolAddress((void**)&q, g_q);
  cudaGetSymbolAddress((void**)&k, g_k);
  cudaGetSymbolAddress((void**)&vT, g_vT);
  cudaGetSymbolAddress((void**)&a, g_a);

  cudaFuncSetAttribute(tc_gemm_k, cudaFuncAttributeMaxDynamicSharedMemorySize,
                       SMEM_TOTAL);

  dim3 blk(256, 1, 1);
  const float scale = 1.0f / sqrtf((float)kD);

  // Stage 0: RNE-convert all inputs in ONE full-chip launch (z = 5 planes)
  cvt5_kernel<<<dim3(592, 1, 5), blk>>>(x, xc, y, yc, Wq, wqc, Wk, wkc,
                                        Wv, wvc, kNX * kC, kD * kC);

  // Stage 1 (fused): q, k, vT
  dim3 gP(kD / BN, kNX / BM, 3);
  tc_gemm_k<<<gP, blk, SMEM_TOTAL>>>(xc, wqc, q, yc, wkc, k, yc, wvc, vT,
                                     kNX, kD, kC, 1.0f, 1, 0);

  // Stage 2: a = mask(q k^T) * scale
  dim3 gA(kNY / BN, kNX / BM, 1);
  tc_gemm_k<<<gA, blk, SMEM_TOTAL>>>(q, k, a, nullptr, nullptr, nullptr,
                                     nullptr, nullptr, nullptr,
                                     kNX, kNY, kD, scale, 0, 2);

  // Stage 3: out = a * vT^T (per-row-block K limit, reversed order)
  dim3 gO(kD / BN, kNX / BM, 1);
  tc_gemm_k<<<gO, blk, SMEM_TOTAL>>>(a, vT, out, nullptr, nullptr, nullptr,
                                     nullptr, nullptr, nullptr,
                                     kNX, kD, kNY, 1.0f, 0, 3);
}